// round 13
// baseline (speedup 1.0000x reference)
#include <cuda_runtime.h>
#include <cstdint>

// ---------------- problem constants ----------------
#define D_DIM 1024
#define ER    256
#define NL    3
#define BM    32
#define NTHR  256
#define NBLK  (32768 / BM)   // 1024

// smem strides
#define XSTR 68              // 64 + 4 pad -> a-frag LDS conflict-free (68%32==4)
#define VSTR 260             // 256 + 4 pad
#define ESTR 132             // epilogue stage stride

// smem float offsets
#define OFF_XS   0           // [3][32][68] = 6528 ; aliases: gpart [8][32][8]=2048, epi stage [32][132]=4224
#define OFF_VS   6528        // [32][260]   = 8320  (v1 -> then w)
#define OFF_GATE 14848       // [32][4]     = 128
#define SMEM_FL  14976
#define SMEM_BYTES (SMEM_FL * 4)   // 59904 B -> 3 CTAs/SM

// ---------------- packed weights (fragment-major: [k8][n32][tt(8)][g(8)][nt(4)]) ----------------
__device__ float gVp[NL * ER * D_DIM];   // GEMM1 B: k=1024 (k8=128), n=256 (n32=8)
__device__ float gUp[NL * ER * D_DIM];   // GEMM3 B: k=256  (k8=32),  n=1024 (n32=32)
__device__ float gCp[NL * ER * ER];      // GEMM2 B: k=256  (k8=32),  n=256 (n32=8), block-diag
__device__ float gGp[8192];              // gating B: [k8=128][tt(8)][g(8)], cols>=4 zero

// ---------------- helpers ----------------
__device__ __forceinline__ float rna_tf32(float x) {
    uint32_t u; asm("cvt.rna.tf32.f32 %0, %1;" : "=r"(u) : "f"(x));
    return __uint_as_float(u);
}
__device__ __forceinline__ uint32_t fu(float x) { return __float_as_uint(x); }

__device__ __forceinline__ void mma_tf32(float* d,
                                         uint32_t a0, uint32_t a1, uint32_t a2, uint32_t a3,
                                         uint32_t b0, uint32_t b1) {
    asm volatile(
        "mma.sync.aligned.m16n8k8.row.col.f32.tf32.tf32.f32 "
        "{%0,%1,%2,%3}, {%4,%5,%6,%7}, {%8,%9}, {%0,%1,%2,%3};\n"
        : "+f"(d[0]), "+f"(d[1]), "+f"(d[2]), "+f"(d[3])
        : "r"(a0), "r"(a1), "r"(a2), "r"(a3), "r"(b0), "r"(b1));
}
#define MMA4(accp, A0, A1, A2, A3, b0q, b1q)                                  \
    mma_tf32((accp) + 0,  A0, A1, A2, A3, fu((b0q).x), fu((b1q).x));          \
    mma_tf32((accp) + 4,  A0, A1, A2, A3, fu((b0q).y), fu((b1q).y));          \
    mma_tf32((accp) + 8,  A0, A1, A2, A3, fu((b0q).z), fu((b1q).z));          \
    mma_tf32((accp) + 12, A0, A1, A2, A3, fu((b0q).w), fu((b1q).w));

__device__ __forceinline__ void cp16(uint32_t saddr, const float* g) {
    asm volatile("cp.async.cg.shared.global [%0], [%1], 16;\n" :: "r"(saddr), "l"(g));
}
#define CP_COMMIT() asm volatile("cp.async.commit_group;\n" ::: "memory")
#define CP_WAIT(n)  asm volatile("cp.async.wait_group %0;\n" :: "n"(n) : "memory")

// ---------------- weight prep: tf32 round + fragment-major packing ----------------
__global__ void prep_k(const float* __restrict__ U, const float* __restrict__ V,
                       const float* __restrict__ C, const float* __restrict__ gw) {
    const int stride = gridDim.x * blockDim.x;
    const int t0 = blockIdx.x * blockDim.x + threadIdx.x;

    // Vp & Up: each NL*262144
    for (int i = t0; i < NL * ER * D_DIM; i += stride) {
        const int l = i >> 18;
        const int rem = i & 262143;
        {   // Vp: k8 = rem>>11 (128), n32 = (rem>>8)&7, tt, g, nt
            const int k8 = rem >> 11, n32 = (rem >> 8) & 7;
            const int tt = (rem >> 5) & 7, g = (rem >> 2) & 7, nt = rem & 3;
            const int n = n32 * 32 + nt * 8 + g;
            const int d = k8 * 8 + tt;
            const int e = n >> 6, r = n & 63;
            gVp[i] = rna_tf32(V[(((l * 4 + e) * D_DIM + d) * 64) + r]);
        }
        {   // Up: k8 = rem>>13 (32), n32 = (rem>>8)&31, tt, g, nt
            const int k8 = rem >> 13, n32 = (rem >> 8) & 31;
            const int tt = (rem >> 5) & 7, g = (rem >> 2) & 7, nt = rem & 3;
            const int k = k8 * 8 + tt;
            const int n = n32 * 32 + nt * 8 + g;
            const int e = k >> 6, r = k & 63;
            gUp[i] = rna_tf32(U[(((l * 4 + e) * D_DIM + n) * 64) + r]);
        }
    }
    // Cp: NL*65536, block-diagonal
    for (int i = t0; i < NL * ER * ER; i += stride) {
        const int l = i >> 16;
        const int rem = i & 65535;
        const int k8 = rem >> 11, n32 = (rem >> 8) & 7;
        const int tt = (rem >> 5) & 7, g = (rem >> 2) & 7, nt = rem & 3;
        const int k = k8 * 8 + tt;
        const int n = n32 * 32 + nt * 8 + g;
        const int ek = k >> 6, en = n >> 6;
        gCp[i] = (ek == en)
            ? rna_tf32(C[(((l * 4 + en) * 64 + (n & 63)) * 64) + (k & 63)])
            : 0.0f;
    }
    // Gp: [k8=128][tt(8)][g(8)]
    for (int i = t0; i < 8192; i += stride) {
        const int k8 = i >> 6, tt = (i >> 3) & 7, g = i & 7;
        gGp[i] = (g < 4) ? rna_tf32(gw[g * D_DIM + k8 * 8 + tt]) : 0.0f;
    }
}

// ---------------- fused layer kernel ----------------
__global__ void __launch_bounds__(NTHR, 3)
layer_k(const float* __restrict__ xin, float* __restrict__ xout,
        const float* __restrict__ x0g, const float* __restrict__ bias_all,
        int l, int x0_is_xin) {
    extern __shared__ float sm[];
    float* xs    = sm + OFF_XS;
    float* vS    = sm + OFF_VS;
    float* gpart = sm + OFF_XS;     // alias (xs dead when used)
    float* stg   = sm + OFF_XS;     // alias (phase C epilogue)
    float* gateS = sm + OFF_GATE;
    uint32_t sbase = (uint32_t)__cvta_generic_to_shared(sm);

    const int tid = threadIdx.x;
    const int warp = tid >> 5, lane = tid & 31;
    const int g = lane >> 2, t = lane & 3;
    const int nbase = warp * 32;
    const int brow = blockIdx.x * BM;

    const float4* __restrict__ vp4 = (const float4*)(gVp + (size_t)l * (ER * D_DIM));
    const float4* __restrict__ up4 = (const float4*)(gUp + (size_t)l * (ER * D_DIM));
    const float4* __restrict__ cp4 = (const float4*)(gCp + (size_t)l * (ER * ER));
    const float* bl = bias_all + l * D_DIM;

    float acc[32];
    float gacc[8];
    #pragma unroll
    for (int i = 0; i < 32; i++) acc[i] = 0.0f;
    #pragma unroll
    for (int i = 0; i < 8; i++) gacc[i] = 0.0f;

    // x chunk loader: 32 rows x 64 floats into stage s
    auto load_x = [&](int s, int k0) {
        #pragma unroll
        for (int j = 0; j < 2; j++) {
            int u = tid + j * 256;
            int row = u >> 4, c4 = u & 15;
            cp16(sbase + (uint32_t)((s * 2176 + row * XSTR + c4 * 4) * 4),
                 xin + (size_t)(brow + row) * D_DIM + k0 + c4 * 4);
        }
    };

    // ============ Phase A: v1_pre = x @ V (M=32,N=256,K=1024) + gating, B from L2 ============
    load_x(0, 0);  CP_COMMIT();
    load_x(1, 64); CP_COMMIT();

    for (int c = 0; c < 16; c++) {
        if (c < 15) { CP_WAIT(1); } else { CP_WAIT(0); }
        __syncthreads();
        if (c + 2 < 16) { load_x((c + 2) % 3, (c + 2) * 64); CP_COMMIT(); }

        const float* xb = xs + (c % 3) * 2176;
        const bool dogate = ((c & 7) == (warp & 7));
        #pragma unroll
        for (int ks = 0; ks < 8; ks++) {
            const int k8 = c * 8 + ks;
            const int kb = ks * 8;
            uint32_t a0 = fu(rna_tf32(xb[g * XSTR + kb + t]));
            uint32_t a1 = fu(rna_tf32(xb[(g + 8) * XSTR + kb + t]));
            uint32_t a2 = fu(rna_tf32(xb[g * XSTR + kb + t + 4]));
            uint32_t a3 = fu(rna_tf32(xb[(g + 8) * XSTR + kb + t + 4]));
            uint32_t a4 = fu(rna_tf32(xb[(16 + g) * XSTR + kb + t]));
            uint32_t a5 = fu(rna_tf32(xb[(24 + g) * XSTR + kb + t]));
            uint32_t a6 = fu(rna_tf32(xb[(16 + g) * XSTR + kb + t + 4]));
            uint32_t a7 = fu(rna_tf32(xb[(24 + g) * XSTR + kb + t + 4]));
            const int bidx = (k8 * 8 + warp) * 8;
            float4 b0q = __ldg(vp4 + (size_t)(bidx + t) * 8 + g);
            float4 b1q = __ldg(vp4 + (size_t)(bidx + t + 4) * 8 + g);
            MMA4(acc,      a0, a1, a2, a3, b0q, b1q);
            MMA4(acc + 16, a4, a5, a6, a7, b0q, b1q);
            if (dogate) {
                uint32_t gb0 = fu(__ldg(gGp + k8 * 64 + t * 8 + g));
                uint32_t gb1 = fu(__ldg(gGp + k8 * 64 + (t + 4) * 8 + g));
                mma_tf32(gacc,     a0, a1, a2, a3, gb0, gb1);
                mma_tf32(gacc + 4, a4, a5, a6, a7, gb0, gb1);
            }
        }
    }
    __syncthreads();   // all warps done with last x stage before gpart aliases it

    // v1 = rna(tanh(acc)) -> vS ; gating partials -> gpart
    #pragma unroll
    for (int mt = 0; mt < 2; mt++) {
        const int r0 = mt * 16 + g;
        #pragma unroll
        for (int nt = 0; nt < 4; nt++) {
            const int col = nbase + nt * 8 + 2 * t;
            vS[r0 * VSTR + col]           = rna_tf32(tanhf(acc[mt * 16 + nt * 4 + 0]));
            vS[r0 * VSTR + col + 1]       = rna_tf32(tanhf(acc[mt * 16 + nt * 4 + 1]));
            vS[(r0 + 8) * VSTR + col]     = rna_tf32(tanhf(acc[mt * 16 + nt * 4 + 2]));
            vS[(r0 + 8) * VSTR + col + 1] = rna_tf32(tanhf(acc[mt * 16 + nt * 4 + 3]));
        }
        const int cc = 2 * t;
        gpart[warp * 256 + r0 * 8 + cc]           = gacc[mt * 4 + 0];
        gpart[warp * 256 + r0 * 8 + cc + 1]       = gacc[mt * 4 + 1];
        gpart[warp * 256 + (r0 + 8) * 8 + cc]     = gacc[mt * 4 + 2];
        gpart[warp * 256 + (r0 + 8) * 8 + cc + 1] = gacc[mt * 4 + 3];
    }
    __syncthreads();

    // softmax over experts
    if (tid < 128) {
        const int row = tid >> 2, e = tid & 3;
        float s = 0.0f;
        #pragma unroll
        for (int w = 0; w < 8; w++) s += gpart[w * 256 + row * 8 + e];
        float m = s;
        m = fmaxf(m, __shfl_xor_sync(0xffffffffu, m, 1));
        m = fmaxf(m, __shfl_xor_sync(0xffffffffu, m, 2));
        float p = __expf(s - m);
        float su = p;
        su += __shfl_xor_sync(0xffffffffu, su, 1);
        su += __shfl_xor_sync(0xffffffffu, su, 2);
        gateS[tid] = p / su;
    }
    __syncthreads();

    // ============ Phase B: v2_pre = v1 @ C (M=32,N=256,K=256), no barriers in loop ============
    #pragma unroll
    for (int i = 0; i < 32; i++) acc[i] = 0.0f;
    #pragma unroll 4
    for (int k8 = 0; k8 < 32; k8++) {
        const int k = k8 * 8;
        uint32_t a0 = fu(vS[g * VSTR + k + t]);
        uint32_t a1 = fu(vS[(g + 8) * VSTR + k + t]);
        uint32_t a2 = fu(vS[g * VSTR + k + t + 4]);
        uint32_t a3 = fu(vS[(g + 8) * VSTR + k + t + 4]);
        uint32_t a4 = fu(vS[(16 + g) * VSTR + k + t]);
        uint32_t a5 = fu(vS[(24 + g) * VSTR + k + t]);
        uint32_t a6 = fu(vS[(16 + g) * VSTR + k + t + 4]);
        uint32_t a7 = fu(vS[(24 + g) * VSTR + k + t + 4]);
        const int bidx = (k8 * 8 + warp) * 8;
        float4 b0q = __ldg(cp4 + (size_t)(bidx + t) * 8 + g);
        float4 b1q = __ldg(cp4 + (size_t)(bidx + t + 4) * 8 + g);
        MMA4(acc,      a0, a1, a2, a3, b0q, b1q);
        MMA4(acc + 16, a4, a5, a6, a7, b0q, b1q);
    }
    __syncthreads();   // all reads of v1 done before overwrite

    // w = rna(gate * tanh(v2_pre)) -> vS
    #pragma unroll
    for (int mt = 0; mt < 2; mt++) {
        const int r0 = mt * 16 + g;
        #pragma unroll
        for (int nt = 0; nt < 4; nt++) {
            const int col = nbase + nt * 8 + 2 * t;   // col,col+1 share expert block
            const int e = col >> 6;
            const float g0 = gateS[r0 * 4 + e];
            const float g1 = gateS[(r0 + 8) * 4 + e];
            vS[r0 * VSTR + col]           = rna_tf32(g0 * tanhf(acc[mt * 16 + nt * 4 + 0]));
            vS[r0 * VSTR + col + 1]       = rna_tf32(g0 * tanhf(acc[mt * 16 + nt * 4 + 1]));
            vS[(r0 + 8) * VSTR + col]     = rna_tf32(g1 * tanhf(acc[mt * 16 + nt * 4 + 2]));
            vS[(r0 + 8) * VSTR + col + 1] = rna_tf32(g1 * tanhf(acc[mt * 16 + nt * 4 + 3]));
        }
    }
    __syncthreads();

    // ============ Phase C: out = w @ U (M=32,N=1024 in 4 passes of 256, K=256) ============
    for (int p = 0; p < 4; p++) {
        #pragma unroll
        for (int i = 0; i < 32; i++) acc[i] = 0.0f;
        #pragma unroll 4
        for (int k8 = 0; k8 < 32; k8++) {
            const int k = k8 * 8;
            uint32_t a0 = fu(vS[g * VSTR + k + t]);
            uint32_t a1 = fu(vS[(g + 8) * VSTR + k + t]);
            uint32_t a2 = fu(vS[g * VSTR + k + t + 4]);
            uint32_t a3 = fu(vS[(g + 8) * VSTR + k + t + 4]);
            uint32_t a4 = fu(vS[(16 + g) * VSTR + k + t]);
            uint32_t a5 = fu(vS[(24 + g) * VSTR + k + t]);
            uint32_t a6 = fu(vS[(16 + g) * VSTR + k + t + 4]);
            uint32_t a7 = fu(vS[(24 + g) * VSTR + k + t + 4]);
            const int bidx = (k8 * 32 + p * 8 + warp) * 8;
            float4 b0q = __ldg(up4 + (size_t)(bidx + t) * 8 + g);
            float4 b1q = __ldg(up4 + (size_t)(bidx + t + 4) * 8 + g);
            MMA4(acc,      a0, a1, a2, a3, b0q, b1q);
            MMA4(acc + 16, a4, a5, a6, a7, b0q, b1q);
        }

        // epilogue in two 128-col halves staged through smem for coalesced gmem RMW
        for (int h = 0; h < 2; h++) {
            if ((warp >> 2) == h) {
                const int lc = (warp & 3) * 32;
                #pragma unroll
                for (int mt = 0; mt < 2; mt++) {
                    const int r0 = mt * 16 + g;
                    #pragma unroll
                    for (int nt = 0; nt < 4; nt++) {
                        const int col = lc + nt * 8 + 2 * t;
                        stg[r0 * ESTR + col]           = acc[mt * 16 + nt * 4 + 0];
                        stg[r0 * ESTR + col + 1]       = acc[mt * 16 + nt * 4 + 1];
                        stg[(r0 + 8) * ESTR + col]     = acc[mt * 16 + nt * 4 + 2];
                        stg[(r0 + 8) * ESTR + col + 1] = acc[mt * 16 + nt * 4 + 3];
                    }
                }
            }
            __syncthreads();
            #pragma unroll
            for (int it = 0; it < 4; it++) {
                const int i2 = tid + it * 256;
                const int rr = i2 >> 5, c4 = i2 & 31;
                const int gr = brow + rr;
                const int gc = p * 256 + h * 128 + c4 * 4;
                float4 s4 = *reinterpret_cast<const float4*>(stg + rr * ESTR + c4 * 4);
                float4 xv = *reinterpret_cast<const float4*>(xin + (size_t)gr * D_DIM + gc);
                float4 x0v = x0_is_xin ? xv
                           : *reinterpret_cast<const float4*>(x0g + (size_t)gr * D_DIM + gc);
                float4 bv = *reinterpret_cast<const float4*>(bl + gc);
                float4 o;
                o.x = xv.x + x0v.x * (s4.x + bv.x);
                o.y = xv.y + x0v.y * (s4.y + bv.y);
                o.z = xv.z + x0v.z * (s4.z + bv.z);
                o.w = xv.w + x0v.w * (s4.w + bv.w);
                *reinterpret_cast<float4*>(xout + (size_t)gr * D_DIM + gc) = o;
            }
            __syncthreads();
        }
    }
}

// ---------------- launch ----------------
extern "C" void kernel_launch(void* const* d_in, const int* in_sizes, int n_in,
                              void* d_out, int out_size) {
    const float* inputs = (const float*)d_in[0];
    const float* U      = (const float*)d_in[1];
    const float* V      = (const float*)d_in[2];
    const float* C      = (const float*)d_in[3];
    const float* gw     = (const float*)d_in[4];
    const float* bias   = (const float*)d_in[5];
    float* out = (float*)d_out;
    (void)in_sizes; (void)n_in; (void)out_size;

    cudaFuncSetAttribute(layer_k, cudaFuncAttributeMaxDynamicSharedMemorySize, SMEM_BYTES);

    prep_k<<<512, 256>>>(U, V, C, gw);
    layer_k<<<NBLK, NTHR, SMEM_BYTES>>>(inputs, out, inputs, bias, 0, 1);
    layer_k<<<NBLK, NTHR, SMEM_BYTES>>>(out,    out, inputs, bias, 1, 0);
    layer_k<<<NBLK, NTHR, SMEM_BYTES>>>(out,    out, inputs, bias, 2, 0);
}

// round 14
// speedup vs baseline: 1.3145x; 1.3145x over previous
#include <cuda_runtime.h>
#include <cstdint>

// ---------------- problem constants ----------------
#define D_DIM 1024
#define ER    256
#define NL    3
#define BM    32
#define NTHR  256
#define NBLK  (32768 / BM)   // 1024
#define KC    16             // K-chunk

// smem strides (floats)
#define BSTR 264             // B tile row stride (264%32==8 -> b-frag conflict-free)
#define VSTR 260             // vS row stride (260%32==4 -> a-frag conflict-free)
#define XSTR 20              // x chunk row stride (g*20+t covers all 32 banks)
#define ESTR 264             // epilogue stage stride (aliases Bs exactly)

// smem float offsets
#define OFF_BS   0           // [2][16][264] = 8448 ; aliases: gpart [8][32][8]=2048, epi [32][264]=8448
#define OFF_VS   8448        // [32][260] = 8320
#define OFF_XS   16768       // [2][32][20] = 1280
#define OFF_GWS  18048       // [2][16][8] = 256
#define OFF_GATE 18304       // [32][4] = 128
#define SMEM_FL  18432
#define SMEM_BYTES (SMEM_FL * 4)   // 73728 B -> 3 CTAs/SM

#define BS_STG 4224          // stage stride: 16*264
#define XS_STG 640           // 32*20
#define GW_STG 128           // 16*8

// ---------------- prepped weights (layouts verified passing in R10) ----------------
__device__ float g_Vt[NL * D_DIM * ER];    // [l][d][er]   B for GEMM1 (rows=k=d)
__device__ float g_Ut[NL * ER * D_DIM];    // [l][er][d]   B for GEMM3 (rows=k=er)
__device__ float g_Cb[NL * ER * ER];       // [l][k][n]    block-diag C
__device__ float g_gwT[D_DIM * 8];         // [d][e]       gating B (e>=4 zero)

// ---------------- helpers ----------------
__device__ __forceinline__ float rna_tf32(float x) {
    uint32_t u; asm("cvt.rna.tf32.f32 %0, %1;" : "=r"(u) : "f"(x));
    return __uint_as_float(u);
}
__device__ __forceinline__ uint32_t fu(float x) { return __float_as_uint(x); }

__device__ __forceinline__ void mma_tf32(float* d,
                                         uint32_t a0, uint32_t a1, uint32_t a2, uint32_t a3,
                                         uint32_t b0, uint32_t b1) {
    asm volatile(
        "mma.sync.aligned.m16n8k8.row.col.f32.tf32.tf32.f32 "
        "{%0,%1,%2,%3}, {%4,%5,%6,%7}, {%8,%9}, {%0,%1,%2,%3};\n"
        : "+f"(d[0]), "+f"(d[1]), "+f"(d[2]), "+f"(d[3])
        : "r"(a0), "r"(a1), "r"(a2), "r"(a3), "r"(b0), "r"(b1));
}

__device__ __forceinline__ void cp16(uint32_t saddr, const float* g) {
    asm volatile("cp.async.cg.shared.global [%0], [%1], 16;\n" :: "r"(saddr), "l"(g));
}
#define CP_COMMIT() asm volatile("cp.async.commit_group;\n" ::: "memory")
#define CP_WAIT0()  asm volatile("cp.async.wait_group 0;\n" ::: "memory")

// ---------------- weight prep (identical index math to the 1076us run) ----------------
__global__ void prep_k(const float* __restrict__ U, const float* __restrict__ V,
                       const float* __restrict__ C, const float* __restrict__ gw) {
    const int stride = gridDim.x * blockDim.x;
    const int t0 = blockIdx.x * blockDim.x + threadIdx.x;

    for (int i = t0; i < NL * D_DIM * ER; i += stride) {
        const int l = i / (D_DIM * ER);
        const int rem = i % (D_DIM * ER);
        {   // Vt[l][d][e*64+r] = V[l,e,d,r]
            const int d = rem >> 8, n = rem & 255, e = n >> 6, r = n & 63;
            g_Vt[i] = rna_tf32(V[(((l * 4 + e) * D_DIM + d) * 64) + r]);
        }
        {   // Ut[l][e*64+r][d] = U[l,e,d,r]
            const int er = rem >> 10, d = rem & 1023, e = er >> 6, r = er & 63;
            g_Ut[i] = rna_tf32(U[(((l * 4 + e) * D_DIM + d) * 64) + r]);
        }
    }
    for (int i = t0; i < NL * ER * ER; i += stride) {
        const int l = i / (ER * ER);
        const int rem = i % (ER * ER);
        const int sg = rem >> 8, rg = rem & 255;
        const int es = sg >> 6, er_ = rg >> 6;
        g_Cb[i] = (es == er_)
            ? rna_tf32(C[(((l * 4 + es) * 64 + (rg & 63)) * 64) + (sg & 63)])
            : 0.0f;
    }
    for (int i = t0; i < D_DIM * 8; i += stride) {
        const int d = i >> 3, e = i & 7;
        g_gwT[i] = (e < 4) ? rna_tf32(gw[e * D_DIM + d]) : 0.0f;
    }
}

// ---------------- fused layer kernel ----------------
__global__ void __launch_bounds__(NTHR, 3)
layer_k(const float* __restrict__ xin, float* __restrict__ xout,
        const float* __restrict__ x0g, const float* __restrict__ bias_all,
        int l, int x0_is_xin) {
    extern __shared__ float sm[];
    float* Bs    = sm + OFF_BS;
    float* vS    = sm + OFF_VS;
    float* xs    = sm + OFF_XS;
    float* gws   = sm + OFF_GWS;
    float* gateS = sm + OFF_GATE;
    float* gpart = sm + OFF_BS;   // alias Bs (free between phase A and phase B prologue)
    float* stg   = sm + OFF_BS;   // alias Bs (free after each phase-C chunk loop)
    uint32_t sbase = (uint32_t)__cvta_generic_to_shared(sm);

    const int tid = threadIdx.x;
    const int warp = tid >> 5, lane = tid & 31;
    const int g = lane >> 2, t = lane & 3;
    const int nbase = warp * 32;
    const int brow = blockIdx.x * BM;

    const float* Vt = g_Vt + (size_t)l * (D_DIM * ER);
    const float* Ut = g_Ut + (size_t)l * (ER * D_DIM);
    const float* Cb = g_Cb + (size_t)l * (ER * ER);
    const float* bl = bias_all + l * D_DIM;

    float acc[32];
    float gacc[8];
    #pragma unroll
    for (int i = 0; i < 32; i++) acc[i] = 0.0f;
    #pragma unroll
    for (int i = 0; i < 8; i++) gacc[i] = 0.0f;

    // ---- loaders: one 16-row K-chunk of B (256 cols), x (32x16), gating (16x8) ----
    auto load_B = [&](int s, const float* src, int row0, int srcstride, int coloff) {
        #pragma unroll
        for (int j = 0; j < 4; j++) {
            int u = tid + j * 256;
            int r = u >> 6, c4 = u & 63;
            cp16(sbase + (uint32_t)((OFF_BS + s * BS_STG + r * BSTR + c4 * 4) * 4),
                 src + (size_t)(row0 + r) * srcstride + coloff + c4 * 4);
        }
    };
    auto load_x = [&](int s, int k0) {
        if (tid < 128) {
            int r = tid >> 2, c4 = tid & 3;
            cp16(sbase + (uint32_t)((OFF_XS + s * XS_STG + r * XSTR + c4 * 4) * 4),
                 xin + (size_t)(brow + r) * D_DIM + k0 + c4 * 4);
        }
    };
    auto load_g = [&](int s, int k0) {
        if (tid < 32) {
            int r = tid >> 1, c4 = tid & 1;
            cp16(sbase + (uint32_t)((OFF_GWS + s * GW_STG + r * 8 + c4 * 4) * 4),
                 g_gwT + (k0 + r) * 8 + c4 * 4);
        }
    };

    // ============ Phase A: v1_pre = x @ Vt (M=32,N=256,K=1024) + gating ============
    load_B(0, Vt, 0, ER, 0); load_x(0, 0); load_g(0, 0); CP_COMMIT();

    for (int c = 0; c < 64; c++) {
        CP_WAIT0();
        __syncthreads();
        const int s = c & 1;
        if (c + 1 < 64) {
            load_B(s ^ 1, Vt, (c + 1) * KC, ER, 0);
            load_x(s ^ 1, (c + 1) * KC);
            load_g(s ^ 1, (c + 1) * KC);
            CP_COMMIT();
        }
        const float* xb = xs + s * XS_STG;
        const float* bb = Bs + s * BS_STG;
        const float* gb = gws + s * GW_STG;
        const bool dogate = ((c & 7) == warp);
        #pragma unroll
        for (int kk = 0; kk < 2; kk++) {
            const int kb = kk * 8;
            // A fragments: raw fp32 bits (HW tf32 truncation) — no cvt
            uint32_t a0 = fu(xb[g * XSTR + kb + t]);
            uint32_t a1 = fu(xb[(g + 8) * XSTR + kb + t]);
            uint32_t a2 = fu(xb[g * XSTR + kb + t + 4]);
            uint32_t a3 = fu(xb[(g + 8) * XSTR + kb + t + 4]);
            uint32_t a4 = fu(xb[(16 + g) * XSTR + kb + t]);
            uint32_t a5 = fu(xb[(24 + g) * XSTR + kb + t]);
            uint32_t a6 = fu(xb[(16 + g) * XSTR + kb + t + 4]);
            uint32_t a7 = fu(xb[(24 + g) * XSTR + kb + t + 4]);
            #pragma unroll
            for (int nt = 0; nt < 4; nt++) {
                const int col = nbase + nt * 8 + g;
                uint32_t b0 = fu(bb[(kb + t) * BSTR + col]);
                uint32_t b1 = fu(bb[(kb + t + 4) * BSTR + col]);
                mma_tf32(acc + nt * 4,      a0, a1, a2, a3, b0, b1);
                mma_tf32(acc + 16 + nt * 4, a4, a5, a6, a7, b0, b1);
            }
            if (dogate) {
                uint32_t gb0 = fu(gb[(kb + t) * 8 + g]);
                uint32_t gb1 = fu(gb[(kb + t + 4) * 8 + g]);
                mma_tf32(gacc,     a0, a1, a2, a3, gb0, gb1);
                mma_tf32(gacc + 4, a4, a5, a6, a7, gb0, gb1);
            }
        }
    }
    __syncthreads();   // all compute done before gpart aliases Bs

    // v1 = rna(tanh(acc)) -> vS ; gating partials -> gpart
    #pragma unroll
    for (int mt = 0; mt < 2; mt++) {
        const int r0 = mt * 16 + g;
        #pragma unroll
        for (int nt = 0; nt < 4; nt++) {
            const int col = nbase + nt * 8 + 2 * t;
            vS[r0 * VSTR + col]           = rna_tf32(tanhf(acc[mt * 16 + nt * 4 + 0]));
            vS[r0 * VSTR + col + 1]       = rna_tf32(tanhf(acc[mt * 16 + nt * 4 + 1]));
            vS[(r0 + 8) * VSTR + col]     = rna_tf32(tanhf(acc[mt * 16 + nt * 4 + 2]));
            vS[(r0 + 8) * VSTR + col + 1] = rna_tf32(tanhf(acc[mt * 16 + nt * 4 + 3]));
        }
        const int cc = 2 * t;
        gpart[warp * 256 + r0 * 8 + cc]           = gacc[mt * 4 + 0];
        gpart[warp * 256 + r0 * 8 + cc + 1]       = gacc[mt * 4 + 1];
        gpart[warp * 256 + (r0 + 8) * 8 + cc]     = gacc[mt * 4 + 2];
        gpart[warp * 256 + (r0 + 8) * 8 + cc + 1] = gacc[mt * 4 + 3];
    }
    __syncthreads();

    // softmax over experts
    if (tid < 128) {
        const int row = tid >> 2, e = tid & 3;
        float s = 0.0f;
        #pragma unroll
        for (int w = 0; w < 8; w++) s += gpart[w * 256 + row * 8 + e];
        float m = s;
        m = fmaxf(m, __shfl_xor_sync(0xffffffffu, m, 1));
        m = fmaxf(m, __shfl_xor_sync(0xffffffffu, m, 2));
        float p = __expf(s - m);
        float su = p;
        su += __shfl_xor_sync(0xffffffffu, su, 1);
        su += __shfl_xor_sync(0xffffffffu, su, 2);
        gateS[tid] = p / su;
    }
    __syncthreads();

    // ============ Phase B: v2_pre = v1 @ Cb (M=32,N=256,K=256) ============
    #pragma unroll
    for (int i = 0; i < 32; i++) acc[i] = 0.0f;
    load_B(0, Cb, 0, ER, 0); CP_COMMIT();
    for (int c = 0; c < 16; c++) {
        CP_WAIT0();
        __syncthreads();
        const int s = c & 1;
        if (c + 1 < 16) { load_B(s ^ 1, Cb, (c + 1) * KC, ER, 0); CP_COMMIT(); }
        const float* bb = Bs + s * BS_STG;
        #pragma unroll
        for (int kk = 0; kk < 2; kk++) {
            const int kg = c * KC + kk * 8;
            const int kb = kk * 8;
            uint32_t a0 = fu(vS[g * VSTR + kg + t]);
            uint32_t a1 = fu(vS[(g + 8) * VSTR + kg + t]);
            uint32_t a2 = fu(vS[g * VSTR + kg + t + 4]);
            uint32_t a3 = fu(vS[(g + 8) * VSTR + kg + t + 4]);
            uint32_t a4 = fu(vS[(16 + g) * VSTR + kg + t]);
            uint32_t a5 = fu(vS[(24 + g) * VSTR + kg + t]);
            uint32_t a6 = fu(vS[(16 + g) * VSTR + kg + t + 4]);
            uint32_t a7 = fu(vS[(24 + g) * VSTR + kg + t + 4]);
            #pragma unroll
            for (int nt = 0; nt < 4; nt++) {
                const int col = nbase + nt * 8 + g;
                uint32_t b0 = fu(bb[(kb + t) * BSTR + col]);
                uint32_t b1 = fu(bb[(kb + t + 4) * BSTR + col]);
                mma_tf32(acc + nt * 4,      a0, a1, a2, a3, b0, b1);
                mma_tf32(acc + 16 + nt * 4, a4, a5, a6, a7, b0, b1);
            }
        }
    }
    __syncthreads();   // all reads of v1 finished before overwrite

    // w = rna(gate * tanh(v2_pre)) -> vS
    #pragma unroll
    for (int mt = 0; mt < 2; mt++) {
        const int r0 = mt * 16 + g;
        #pragma unroll
        for (int nt = 0; nt < 4; nt++) {
            const int col = nbase + nt * 8 + 2 * t;   // col,col+1 same expert block
            const int e = col >> 6;
            const float g0 = gateS[r0 * 4 + e];
            const float g1 = gateS[(r0 + 8) * 4 + e];
            vS[r0 * VSTR + col]           = rna_tf32(g0 * tanhf(acc[mt * 16 + nt * 4 + 0]));
            vS[r0 * VSTR + col + 1]       = rna_tf32(g0 * tanhf(acc[mt * 16 + nt * 4 + 1]));
            vS[(r0 + 8) * VSTR + col]     = rna_tf32(g1 * tanhf(acc[mt * 16 + nt * 4 + 2]));
            vS[(r0 + 8) * VSTR + col + 1] = rna_tf32(g1 * tanhf(acc[mt * 16 + nt * 4 + 3]));
        }
    }
    __syncthreads();

    // ============ Phase C: out = w @ Ut (M=32,N=1024 in 4 passes of 256, K=256) ============
    for (int p = 0; p < 4; p++) {
        #pragma unroll
        for (int i = 0; i < 32; i++) acc[i] = 0.0f;
        load_B(0, Ut, 0, D_DIM, p * 256); CP_COMMIT();
        for (int c = 0; c < 16; c++) {
            CP_WAIT0();
            __syncthreads();
            const int s = c & 1;
            if (c + 1 < 16) { load_B(s ^ 1, Ut, (c + 1) * KC, D_DIM, p * 256); CP_COMMIT(); }
            const float* bb = Bs + s * BS_STG;
            #pragma unroll
            for (int kk = 0; kk < 2; kk++) {
                const int kg = c * KC + kk * 8;
                const int kb = kk * 8;
                uint32_t a0 = fu(vS[g * VSTR + kg + t]);
                uint32_t a1 = fu(vS[(g + 8) * VSTR + kg + t]);
                uint32_t a2 = fu(vS[g * VSTR + kg + t + 4]);
                uint32_t a3 = fu(vS[(g + 8) * VSTR + kg + t + 4]);
                uint32_t a4 = fu(vS[(16 + g) * VSTR + kg + t]);
                uint32_t a5 = fu(vS[(24 + g) * VSTR + kg + t]);
                uint32_t a6 = fu(vS[(16 + g) * VSTR + kg + t + 4]);
                uint32_t a7 = fu(vS[(24 + g) * VSTR + kg + t + 4]);
                #pragma unroll
                for (int nt = 0; nt < 4; nt++) {
                    const int col = nbase + nt * 8 + g;
                    uint32_t b0 = fu(bb[(kb + t) * BSTR + col]);
                    uint32_t b1 = fu(bb[(kb + t + 4) * BSTR + col]);
                    mma_tf32(acc + nt * 4,      a0, a1, a2, a3, b0, b1);
                    mma_tf32(acc + 16 + nt * 4, a4, a5, a6, a7, b0, b1);
                }
            }
        }
        __syncthreads();   // Bs free -> stage epilogue there

        // stage all 256 cols -> stg[32][264] (== Bs region), then coalesced RMW
        #pragma unroll
        for (int mt = 0; mt < 2; mt++) {
            const int r0 = mt * 16 + g;
            #pragma unroll
            for (int nt = 0; nt < 4; nt++) {
                const int col = nbase + nt * 8 + 2 * t;
                stg[r0 * ESTR + col]           = acc[mt * 16 + nt * 4 + 0];
                stg[r0 * ESTR + col + 1]       = acc[mt * 16 + nt * 4 + 1];
                stg[(r0 + 8) * ESTR + col]     = acc[mt * 16 + nt * 4 + 2];
                stg[(r0 + 8) * ESTR + col + 1] = acc[mt * 16 + nt * 4 + 3];
            }
        }
        __syncthreads();

        #pragma unroll
        for (int it = 0; it < 8; it++) {
            const int i2 = tid + it * 256;
            const int rr = i2 >> 6, c4 = i2 & 63;
            const int gr = brow + rr;
            const int gc = p * 256 + c4 * 4;
            float4 s4 = *reinterpret_cast<const float4*>(stg + rr * ESTR + c4 * 4);
            float4 xv = *reinterpret_cast<const float4*>(xin + (size_t)gr * D_DIM + gc);
            float4 x0v = x0_is_xin ? xv
                       : *reinterpret_cast<const float4*>(x0g + (size_t)gr * D_DIM + gc);
            float4 bv = *reinterpret_cast<const float4*>(bl + gc);
            float4 o;
            o.x = xv.x + x0v.x * (s4.x + bv.x);
            o.y = xv.y + x0v.y * (s4.y + bv.y);
            o.z = xv.z + x0v.z * (s4.z + bv.z);
            o.w = xv.w + x0v.w * (s4.w + bv.w);
            *reinterpret_cast<float4*>(xout + (size_t)gr * D_DIM + gc) = o;
        }
        __syncthreads();   // stg (Bs) free before next pass prologue
    }
}

// ---------------- launch ----------------
extern "C" void kernel_launch(void* const* d_in, const int* in_sizes, int n_in,
                              void* d_out, int out_size) {
    const float* inputs = (const float*)d_in[0];
    const float* U      = (const float*)d_in[1];
    const float* V      = (const float*)d_in[2];
    const float* C      = (const float*)d_in[3];
    const float* gw     = (const float*)d_in[4];
    const float* bias   = (const float*)d_in[5];
    float* out = (float*)d_out;
    (void)in_sizes; (void)n_in; (void)out_size;

    cudaFuncSetAttribute(layer_k, cudaFuncAttributeMaxDynamicSharedMemorySize, SMEM_BYTES);

    prep_k<<<512, 256>>>(U, V, C, gw);
    layer_k<<<NBLK, NTHR, SMEM_BYTES>>>(inputs, out, inputs, bias, 0, 1);
    layer_k<<<NBLK, NTHR, SMEM_BYTES>>>(out,    out, inputs, bias, 1, 0);
    layer_k<<<NBLK, NTHR, SMEM_BYTES>>>(out,    out, inputs, bias, 2, 0);
}